// round 17
// baseline (speedup 1.0000x reference)
#include <cuda_runtime.h>
#include <math.h>

typedef unsigned long long u64;

#define KW   9
#define PAD  4
#define TXL  32
#define TYL  2
#define PXT  2
#define TW   64
#define TH   2
#define SXU  (TW + 2*PAD)  // 72
#define SXP  76            // padded row stride
#define HH   256
#define WW   256
#define CC   3

#define INV_DIAG (1.0f / 362.03867196751236f)
#define SIGMA_MIN 0.5f
#define SIGMA_RANGE 9.5f
#define PI_F 3.14159265358979323846f

// rows 0..4 of the symmetric 9x9 q-index map (row oy == row 8-oy)
__device__ constexpr int QIDX5[5][9] = {
    {14,13,12,10, 9,10,12,13,14},
    {13,11, 8, 7, 6, 7, 8,11,13},
    {12, 8, 5, 4, 3, 4, 5, 8,12},
    {10, 7, 4, 2, 1, 2, 4, 7,10},
    { 9, 6, 3, 1, 0, 1, 3, 6, 9},
};

__device__ __forceinline__ int reflect_idx(int v) {
    v = (v < 0) ? -v : v;
    return (v >= HH) ? (2 * HH - 2 - v) : v;   // H == W == 256
}

// ---- f32x2 packed ops (sm_100+/sm_103a) ----
__device__ __forceinline__ float2 mul2(float2 a, float2 b) {
    float2 d;
    asm("mul.rn.f32x2 %0, %1, %2;"
        : "=l"(reinterpret_cast<u64&>(d))
        : "l"(reinterpret_cast<const u64&>(a)), "l"(reinterpret_cast<const u64&>(b)));
    return d;
}
__device__ __forceinline__ float2 fma2(float2 a, float2 b, float2 c) {
    float2 d;
    asm("fma.rn.f32x2 %0, %1, %2, %3;"
        : "=l"(reinterpret_cast<u64&>(d))
        : "l"(reinterpret_cast<const u64&>(a)), "l"(reinterpret_cast<const u64&>(b)),
          "l"(reinterpret_cast<const u64&>(c)));
    return d;
}

// Packed unnormalized weights for the 2 pixels: u[q] = (1 - q*a) * E^q (per lane).
// Returns packed 'common' for the final scale.
__device__ __forceinline__ float2 make_weights2(float ddx0, float ddx1, float ddy,
                                                float2* u)
{
    // scalar per-pixel prologue (sqrt/rcp/exp are scalar MUFU anyway)
    const float dyy = ddy * ddy;
    const float d20 = fmaf(ddx0, ddx0, dyy);
    const float d21 = fmaf(ddx1, ddx1, dyy);
    const float di0 = sqrtf(d20), di1 = sqrtf(d21);
    const float s0  = fmaf(SIGMA_RANGE * INV_DIAG, di0, SIGMA_MIN);
    const float s1  = fmaf(SIGMA_RANGE * INV_DIAG, di1, SIGMA_MIN);
    const float s20 = s0 * s0, s21 = s1 * s1;
    const float a0  = 0.5f / s20, a1 = 0.5f / s21;
    const float c0  = -di0 * sqrtf(s0) * __fdividef(1.0f, PI_F * s20 * s20);
    const float c1  = -di1 * sqrtf(s1) * __fdividef(1.0f, PI_F * s21 * s21);

    const float2 E   = make_float2(__expf(-a0), __expf(-a1));
    const float2 E2  = mul2(E, E),   E4  = mul2(E2, E2),  E5  = mul2(E4, E);
    const float2 E8  = mul2(E4, E4), E9  = mul2(E8, E),   E10 = mul2(E8, E2);
    const float2 E13 = mul2(E8, E5), E16 = mul2(E8, E8),  E17 = mul2(E16, E);
    const float2 E18 = mul2(E16,E2), E20 = mul2(E16, E4), E25 = mul2(E16, E9);
    const float2 E32 = mul2(E16, E16);

    // (1 - q*a): scalar FFMA-imm per lane (rt 1), then one packed mul
    #define UQ(idx, Q, EQ) do { \
        float2 om = make_float2(fmaf(-(float)(Q), a0, 1.0f), \
                                fmaf(-(float)(Q), a1, 1.0f)); \
        u[idx] = mul2(om, EQ); } while (0)

    u[0] = make_float2(1.0f, 1.0f);
    UQ(1,  1, E);   UQ(2,  2, E2);  UQ(3,  4, E4);  UQ(4,  5, E5);
    UQ(5,  8, E8);  UQ(6,  9, E9);  UQ(7, 10, E10); UQ(8, 13, E13);
    UQ(9, 16, E16); UQ(10,17, E17); UQ(11,18, E18); UQ(12,20, E20);
    UQ(13,25, E25); UQ(14,32, E32);
    #undef UQ

    return make_float2(c0, c1);
}

// 64-thread CTAs, occ 14 -> 72-reg cap, single wave (14*148 = 2072 >= 2048)
__global__ __launch_bounds__(TXL * TYL, 14)
void adaptive_log_conv(const float* __restrict__ x,
                       const float* __restrict__ foa,
                       float* __restrict__ out)
{
    __shared__ __align__(16) float pr[CC][4][TH][SXP];  // 7.3 KB paired-row sums
    __shared__ __align__(16) float mid[CC][TH][SXP];    // 1.8 KB middle rows

    const int b   = blockIdx.z;
    const int bx0 = blockIdx.x * TW;
    const int by0 = blockIdx.y * TH;
    const int lx  = threadIdx.x;      // 0..31
    const int ly  = threadIdx.y;      // 0..1
    const int tid = ly * TXL + lx;    // 0..63

    const float* xb = x + (size_t)b * CC * HH * WW;

    // ======== pr central: 384 float4 units = 64 thr x (2 'a' x 3 ch) ========
    {
        const int v   = tid & 15;
        const int row = (tid >> 4) & 1;
        const int a0  = tid >> 5;             // 0 or 1
        const int a1  = a0 + 2;               // 2 or 3
        const int ga0 = reflect_idx(by0 + row + a0 - PAD);
        const int gb0 = reflect_idx(by0 + row + 4 - a0);
        const int ga1 = reflect_idx(by0 + row + a1 - PAD);
        const int gb1 = reflect_idx(by0 + row + 4 - a1);
        const int col = bx0 + 4 * v;
        const int sc  = 4 + 4 * v;
        #pragma unroll
        for (int c = 0; c < CC; c++) {
            const float* base = xb + c * (HH * WW);
            float4 p = *(const float4*)(base + ga0 * WW + col);
            float4 q = *(const float4*)(base + gb0 * WW + col);
            float4 r;
            r.x = p.x + q.x; r.y = p.y + q.y; r.z = p.z + q.z; r.w = p.w + q.w;
            *(float4*)&pr[c][a0][row][sc] = r;

            p = *(const float4*)(base + ga1 * WW + col);
            q = *(const float4*)(base + gb1 * WW + col);
            r.x = p.x + q.x; r.y = p.y + q.y; r.z = p.z + q.z; r.w = p.w + q.w;
            *(float4*)&pr[c][a1][row][sc] = r;
        }
    }

    // ======== pr halo: 192 scalars = 64 thr x 3 ch ========
    {
        const int h    = tid & 7;
        const int rowh = (tid >> 3) & 1;
        const int ah   = tid >> 4;            // 0..3
        const int s    = (h < 4) ? h : h + 64;
        const int gx   = reflect_idx(bx0 + s - PAD);
        const int gy1  = reflect_idx(by0 + rowh + ah - PAD);
        const int gy2  = reflect_idx(by0 + rowh + 4 - ah);
        #pragma unroll
        for (int c = 0; c < CC; c++) {
            const float* base = xb + c * (HH * WW);
            pr[c][ah][rowh][s] = base[gy1 * WW + gx] + base[gy2 * WW + gx];
        }
    }

    // ======== mid central: 96 float4 units ========
    {
        const int v   = tid & 15;
        const int row = (tid >> 4) & 1;
        const int c0  = tid >> 5;
        const int col = bx0 + 4 * v;
        const int gy  = (by0 + row) * WW;
        const float4 p = *(const float4*)(xb + c0 * (HH * WW) + gy + col);
        *(float4*)&mid[c0][row][4 + 4 * v] = p;
        if (tid < 32) {
            const float4 p2 = *(const float4*)(xb + 2 * (HH * WW) + gy + col);
            *(float4*)&mid[2][row][4 + 4 * v] = p2;
        }
    }

    // ======== mid halo: 48 scalars ========
    if (tid < 48) {
        const int h   = tid & 7;
        const int row = (tid >> 3) & 1;
        const int c   = tid >> 4;
        const int s   = (h < 4) ? h : h + 64;
        const int gx  = reflect_idx(bx0 + s - PAD);
        mid[c][row][s] = xb[c * (HH * WW) + (by0 + row) * WW + gx];
    }

    // ======== packed weight generation (overlaps in-flight LDGs) ========
    const int px0 = bx0 + PXT * lx;
    const int py  = by0 + ly;
    const float fx  = foa[b * 2 + 0];
    const float fy  = foa[b * 2 + 1];
    const float ddy = (float)py - fy;

    float2 wp[15];
    const float2 common = make_weights2((float)(px0) - fx, (float)(px0 + 1) - fx,
                                        ddy, wp);

    __syncthreads();

    // ======== convolution: f32x2 even taps + scalar odd taps ========
    float2 accp[CC];          // packed (px0, px1) accumulators, even ox
    float  accs0[CC], accs1[CC];
    #pragma unroll
    for (int c = 0; c < CC; c++) {
        accp[c] = make_float2(0.0f, 0.0f);
        accs0[c] = 0.0f; accs1[c] = 0.0f;
    }

    #pragma unroll
    for (int c = 0; c < CC; c++) {
        #pragma unroll
        for (int a = 0; a < 5; a++) {
            const float* row = (a < 4) ? &pr[c][a][ly][PXT * lx]
                                       : &mid[c][ly][PXT * lx];
            const float2 p0 = *(const float2*)(row + 0);   // (t0,t1)
            const float2 p1 = *(const float2*)(row + 2);   // (t2,t3)
            const float2 p2 = *(const float2*)(row + 4);   // (t4,t5)
            const float2 p3 = *(const float2*)(row + 6);   // (t6,t7)
            const float2 p4 = *(const float2*)(row + 8);   // (t8,t9)

            // even ox: packed (t[ox], t[ox+1]) == pk, shared weight index
            accp[c] = fma2(p0, wp[QIDX5[a][0]], accp[c]);
            accp[c] = fma2(p1, wp[QIDX5[a][2]], accp[c]);
            accp[c] = fma2(p2, wp[QIDX5[a][4]], accp[c]);
            accp[c] = fma2(p3, wp[QIDX5[a][6]], accp[c]);
            accp[c] = fma2(p4, wp[QIDX5[a][8]], accp[c]);

            // odd ox: scalar, taps are free sub-register reads
            accs0[c] = fmaf(p0.y, wp[QIDX5[a][1]].x, accs0[c]);
            accs1[c] = fmaf(p1.x, wp[QIDX5[a][1]].y, accs1[c]);
            accs0[c] = fmaf(p1.y, wp[QIDX5[a][3]].x, accs0[c]);
            accs1[c] = fmaf(p2.x, wp[QIDX5[a][3]].y, accs1[c]);
            accs0[c] = fmaf(p2.y, wp[QIDX5[a][5]].x, accs0[c]);
            accs1[c] = fmaf(p3.x, wp[QIDX5[a][5]].y, accs1[c]);
            accs0[c] = fmaf(p3.y, wp[QIDX5[a][7]].x, accs0[c]);
            accs1[c] = fmaf(p4.x, wp[QIDX5[a][7]].y, accs1[c]);
        }
    }

    float* ob = out + (size_t)b * CC * HH * WW;
    #pragma unroll
    for (int c = 0; c < CC; c++) {
        float2 r;
        r.x = (accp[c].x + accs0[c]) * common.x;
        r.y = (accp[c].y + accs1[c]) * common.y;
        *(float2*)&ob[(c * HH + py) * WW + px0] = r;
    }
}

extern "C" void kernel_launch(void* const* d_in, const int* in_sizes, int n_in,
                              void* d_out, int out_size)
{
    const float* x   = (const float*)d_in[0];
    const float* foa = (const float*)d_in[1];
    float* out = (float*)d_out;

    dim3 block(TXL, TYL, 1);
    dim3 grid(WW / TW, HH / TH, 4);   // 2048 CTAs x 64 threads, single wave at occ 14
    adaptive_log_conv<<<grid, block>>>(x, foa, out);
}